// round 2
// baseline (speedup 1.0000x reference)
#include <cuda_runtime.h>
#include <cuda_bf16.h>

// Problem constants
#define NPTS   1048576
#define CIN    64
#define COUT   96
#define NB     4
#define NSEG2  1048576   // 4 * 64^3
#define NSEG4  131072    // 4 * 32^3
#define NSEG8  16384     // 4 * 16^3

// ---------------- static device scratch ----------------
__device__ float g_sums2[(long)NSEG2 * 64];   // 268 MB
__device__ float g_cnt2[NSEG2];
__device__ float g_sums4[(long)NSEG4 * 64];   // 33.5 MB
__device__ float g_cnt4[NSEG4];
__device__ float g_sums8[(long)NSEG8 * 64];   // 4 MB
__device__ float g_cnt8[NSEG8];
__device__ float g_base0[NB * COUT];
__device__ float g_Z8[(long)NSEG8 * COUT];    // 6.3 MB
__device__ float g_Z4[(long)NSEG4 * COUT];    // 50 MB
__device__ int   g_seg2[NPTS];

// ---------------- helpers ----------------
__device__ __forceinline__ void red_add_v4(float* addr, float4 v) {
    asm volatile("red.global.add.v4.f32 [%0], {%1, %2, %3, %4};"
                 :: "l"(addr), "f"(v.x), "f"(v.y), "f"(v.z), "f"(v.w)
                 : "memory");
}

// ---------------- kernel 1: zero scratch ----------------
__global__ void zero_kernel() {
    long tid = (long)blockIdx.x * blockDim.x + threadIdx.x;
    long stride = (long)gridDim.x * blockDim.x;
    float4 z = make_float4(0.f, 0.f, 0.f, 0.f);
    float4* s2 = (float4*)g_sums2;
    for (long i = tid; i < (long)NSEG2 * 16; i += stride) s2[i] = z;
    float4* s4 = (float4*)g_sums4;
    for (long i = tid; i < (long)NSEG4 * 16; i += stride) s4[i] = z;
    float4* s8 = (float4*)g_sums8;
    for (long i = tid; i < (long)NSEG8 * 16; i += stride) s8[i] = z;
    float4* c2 = (float4*)g_cnt2;
    for (long i = tid; i < NSEG2 / 4; i += stride) c2[i] = z;
    float4* c4 = (float4*)g_cnt4;
    for (long i = tid; i < NSEG4 / 4; i += stride) c4[i] = z;
    float4* c8 = (float4*)g_cnt8;
    for (long i = tid; i < NSEG8 / 4; i += stride) c8[i] = z;
}

// ---------------- kernel 2: scatter point features into 3 pyramid levels ----------------
__global__ __launch_bounds__(256) void scatter_kernel(
    const float4* __restrict__ feats4,
    const int* __restrict__ coords,
    const int* __restrict__ batch)
{
    int p = blockIdx.x * 256 + threadIdx.x;
    if (p >= NPTS) return;
    int x = coords[3 * p + 0];
    int y = coords[3 * p + 1];
    int z = coords[3 * p + 2];
    int b = batch[p];

    int s2 = (b << 18) | ((x >> 1) << 12) | ((y >> 1) << 6) | (z >> 1);
    int s4 = (b << 15) | ((x >> 2) << 10) | ((y >> 2) << 5) | (z >> 2);
    int s8 = (b << 12) | ((x >> 3) << 8)  | ((y >> 3) << 4) | (z >> 3);

    g_seg2[p] = s2;

    atomicAdd(&g_cnt2[s2], 1.0f);
    atomicAdd(&g_cnt4[s4], 1.0f);
    atomicAdd(&g_cnt8[s8], 1.0f);

    float* p2 = &g_sums2[(long)s2 * 64];
    float* p4 = &g_sums4[(long)s4 * 64];
    float* p8 = &g_sums8[(long)s8 * 64];
    const float4* f = feats4 + (long)p * 16;
#pragma unroll
    for (int i = 0; i < 16; i++) {
        float4 v = f[i];
        red_add_v4(p2 + 4 * i, v);
        red_add_v4(p4 + 4 * i, v);
        red_add_v4(p8 + 4 * i, v);
    }
}

// ---------------- kernel 3: level-0 reduce + base projection ----------------
__global__ __launch_bounds__(256) void l0_kernel(
    const float* __restrict__ W, const float* __restrict__ bias)
{
    int b = blockIdx.x;
    int tid = threadIdx.x;
    __shared__ float sm[4][64];
    __shared__ float smean[64];
    __shared__ float scnt[256];

    int c = tid & 63, g = tid >> 6;
    const float* base = g_sums8 + (long)b * 4096 * 64;
    float acc = 0.f;
    for (int s = g; s < 4096; s += 4) acc += base[s * 64 + c];
    sm[g][c] = acc;

    float ca = 0.f;
    for (int s = tid; s < 4096; s += 256) ca += g_cnt8[b * 4096 + s];
    scnt[tid] = ca;
    __syncthreads();

    for (int off = 128; off > 0; off >>= 1) {
        if (tid < off) scnt[tid] += scnt[tid + off];
        __syncthreads();
    }
    if (tid < 64) {
        smean[tid] = (sm[0][tid] + sm[1][tid] + sm[2][tid] + sm[3][tid])
                   / fmaxf(scnt[0], 1.0f);
    }
    __syncthreads();
    if (tid < 96) {
        float a = bias[tid];
        const float* wr = W + tid * 256;  // global block = cols [0,64)
#pragma unroll 8
        for (int k = 0; k < 64; k++) a += wr[k] * smean[k];
        g_base0[b * COUT + tid] = a;
    }
}

// ---------------- kernel 4: pyramid transform for levels 8 and 4 ----------------
template <int LEVEL>
__global__ __launch_bounds__(128) void transform_kernel(const float* __restrict__ W)
{
    __shared__ float sh_W[96 * 65];   // [out][k], padded
    __shared__ float sh_m[64 * 36];   // [k][slot]
    __shared__ int   sh_sid[32];

    int tid  = threadIdx.x;
    int base = blockIdx.x * 32;

    if (tid < 32) sh_sid[tid] = base + tid;

    const int WOFS = (LEVEL == 4) ? 128 : 192;
    for (int j = tid; j < 96 * 64; j += 128) {
        int o = j >> 6, c = j & 63;
        sh_W[o * 65 + c] = W[o * 256 + WOFS + c];
    }
    __syncthreads();

    const float* SUMS = (LEVEL == 4) ? g_sums4 : g_sums8;
    const float* CNT  = (LEVEL == 4) ? g_cnt4  : g_cnt8;

    for (int it = tid; it < 512; it += 128) {
        int slot = it >> 4, kc = it & 15;
        int s = sh_sid[slot];
        float4 v = *(const float4*)&SUMS[(long)s * 64 + kc * 4];
        float inv = 1.0f / fmaxf(CNT[s], 1.0f);
        sh_m[(4 * kc + 0) * 36 + slot] = v.x * inv;
        sh_m[(4 * kc + 1) * 36 + slot] = v.y * inv;
        sh_m[(4 * kc + 2) * 36 + slot] = v.z * inv;
        sh_m[(4 * kc + 3) * 36 + slot] = v.w * inv;
    }
    __syncthreads();

    int rt = tid >> 4, ct = tid & 15;
    int r0 = rt * 4, c0 = ct * 6;

    float acc[4][6];
#pragma unroll
    for (int i = 0; i < 4; i++)
#pragma unroll
        for (int j = 0; j < 6; j++) acc[i][j] = 0.f;

#pragma unroll 8
    for (int k = 0; k < 64; k++) {
        float4 m = *(const float4*)&sh_m[k * 36 + r0];
        float mv[4] = {m.x, m.y, m.z, m.w};
        float w[6];
#pragma unroll
        for (int j = 0; j < 6; j++) w[j] = sh_W[(c0 + j) * 65 + k];
#pragma unroll
        for (int i = 0; i < 4; i++)
#pragma unroll
            for (int j = 0; j < 6; j++) acc[i][j] = fmaf(mv[i], w[j], acc[i][j]);
    }

#pragma unroll
    for (int i = 0; i < 4; i++) {
        int s = sh_sid[r0 + i];
        const float* prev;
        float* Zout;
        if (LEVEL == 8) {
            prev = &g_base0[(s >> 12) * COUT];
            Zout = g_Z8;
        } else {
            int bb = s >> 15, xx = (s >> 10) & 31, yy = (s >> 5) & 31, zz = s & 31;
            int s8 = (bb << 12) | ((xx >> 1) << 8) | ((yy >> 1) << 4) | (zz >> 1);
            prev = &g_Z8[(long)s8 * COUT];
            Zout = g_Z4;
        }
        float* dst = &Zout[(long)s * COUT + c0];
#pragma unroll
        for (int j = 0; j < 6; j++) dst[j] = acc[i][j] + prev[c0 + j];
    }
}

// ---------------- kernel 5: fused level-2 transform + output ----------------
// out[p] = Z4[s4(p)] + W2 @ mean2[seg2(p)]
// Block: 192 threads, tile 64 points x 96 outputs. Thread tile 4 pts x 8 outs.
__global__ __launch_bounds__(192) void fused_out_kernel(
    const float* __restrict__ W, float* __restrict__ out)
{
    __shared__ float sh_W[64 * 96];   // [k][out], row stride 96 (384B, 16B-aligned)
    __shared__ float sh_m[64 * 68];   // [k][slot], row stride 68 (272B, 16B-aligned)
    __shared__ int   sh_sid[64];      // seg2 per slot
    __shared__ int   sh_s4[64];       // parent seg4 per slot

    int tid = threadIdx.x;
    int pbase = blockIdx.x * 64;

    if (tid < 64) {
        int s2 = g_seg2[pbase + tid];
        sh_sid[tid] = s2;
        int bb = s2 >> 18, xx = (s2 >> 12) & 63, yy = (s2 >> 6) & 63, zz = s2 & 63;
        sh_s4[tid] = (bb << 15) | ((xx >> 1) << 10) | ((yy >> 1) << 5) | (zz >> 1);
    }

    // stage W2 block: W[o*256 + 64 + k] -> sh_W[k*96 + o]
    for (int j = tid; j < 96 * 64; j += 192) {
        int o = j / 64, c = j & 63;
        sh_W[c * 96 + o] = W[o * 256 + 64 + c];
    }
    __syncthreads();

    // stage means: 64 slots x 16 float4-chunks
    for (int it = tid; it < 1024; it += 192) {
        int slot = it >> 4, kc = it & 15;
        int s = sh_sid[slot];
        float4 v = *(const float4*)&g_sums2[(long)s * 64 + kc * 4];
        float inv = 1.0f / fmaxf(g_cnt2[s], 1.0f);
        sh_m[(4 * kc + 0) * 68 + slot] = v.x * inv;
        sh_m[(4 * kc + 1) * 68 + slot] = v.y * inv;
        sh_m[(4 * kc + 2) * 68 + slot] = v.z * inv;
        sh_m[(4 * kc + 3) * 68 + slot] = v.w * inv;
    }
    __syncthreads();

    // 192 threads = 16 row-threads x 12 col-threads
    int rt = tid & 15, ct = tid >> 4;     // ct in [0,12)
    int r0 = rt * 4, c0 = ct * 8;

    float acc[4][8];
#pragma unroll
    for (int i = 0; i < 4; i++)
#pragma unroll
        for (int j = 0; j < 8; j++) acc[i][j] = 0.f;

#pragma unroll 4
    for (int k = 0; k < 64; k++) {
        float4 m = *(const float4*)&sh_m[k * 68 + r0];
        float4 wa = *(const float4*)&sh_W[k * 96 + c0];
        float4 wb = *(const float4*)&sh_W[k * 96 + c0 + 4];
        float mv[4] = {m.x, m.y, m.z, m.w};
        float wv[8] = {wa.x, wa.y, wa.z, wa.w, wb.x, wb.y, wb.z, wb.w};
#pragma unroll
        for (int i = 0; i < 4; i++)
#pragma unroll
            for (int j = 0; j < 8; j++) acc[i][j] = fmaf(mv[i], wv[j], acc[i][j]);
    }

    // epilogue: add Z4 parent row, write out
#pragma unroll
    for (int i = 0; i < 4; i++) {
        int slot = r0 + i;
        int p = pbase + slot;
        const float* prev = &g_Z4[(long)sh_s4[slot] * COUT + c0];
        float4 pa = *(const float4*)(prev);
        float4 pb = *(const float4*)(prev + 4);
        float4 oa = make_float4(acc[i][0] + pa.x, acc[i][1] + pa.y,
                                acc[i][2] + pa.z, acc[i][3] + pa.w);
        float4 ob = make_float4(acc[i][4] + pb.x, acc[i][5] + pb.y,
                                acc[i][6] + pb.z, acc[i][7] + pb.w);
        float* dst = out + (long)p * COUT + c0;
        *(float4*)(dst)     = oa;
        *(float4*)(dst + 4) = ob;
    }
}

// ---------------- launcher ----------------
extern "C" void kernel_launch(void* const* d_in, const int* in_sizes, int n_in,
                              void* d_out, int out_size)
{
    const float* feats  = (const float*)d_in[0];
    const int*   coords = (const int*)d_in[1];
    const int*   batch  = (const int*)d_in[2];
    const float* W      = (const float*)d_in[3];
    const float* bias   = (const float*)d_in[4];

    zero_kernel<<<2048, 256>>>();
    scatter_kernel<<<NPTS / 256, 256>>>((const float4*)feats, coords, batch);
    l0_kernel<<<NB, 256>>>(W, bias);
    transform_kernel<8><<<NSEG8 / 32, 128>>>(W);
    transform_kernel<4><<<NSEG4 / 32, 128>>>(W);
    fused_out_kernel<<<NPTS / 64, 192>>>(W, (float*)d_out);
}

// round 6
// speedup vs baseline: 1.6157x; 1.6157x over previous
#include <cuda_runtime.h>
#include <cuda_bf16.h>
#include <cstdint>

// Problem constants
#define NPTS   1048576
#define CIN    64
#define COUT   96
#define NB     4
#define NSEG2  1048576   // 4 * 64^3
#define NSEG4  131072    // 4 * 32^3
#define NSEG8  16384     // 4 * 16^3

// ---------------- static device scratch ----------------
__device__ float g_sums2[(long)NSEG2 * 64];   // 268 MB
__device__ float g_cnt2[NSEG2];
__device__ float g_sums4[(long)NSEG4 * 64];   // 33.5 MB
__device__ float g_cnt4[NSEG4];
__device__ float g_sums8[(long)NSEG8 * 64];   // 4 MB
__device__ float g_cnt8[NSEG8];
__device__ float g_base0[NB * COUT];
__device__ float g_Z8[(long)NSEG8 * COUT];    // 6.3 MB
__device__ float g_Z4[(long)NSEG4 * COUT];    // 50 MB
__device__ int   g_seg2[NPTS];

// ---------------- PTX helpers ----------------
__device__ __forceinline__ void red_add_v4(float* addr, float4 v) {
    asm volatile("red.global.add.v4.f32 [%0], {%1, %2, %3, %4};"
                 :: "l"(addr), "f"(v.x), "f"(v.y), "f"(v.z), "f"(v.w)
                 : "memory");
}

// ---------------- kernel 1: zero level-2 scratch only ----------------
__global__ void zero_kernel() {
    long tid = (long)blockIdx.x * blockDim.x + threadIdx.x;
    long stride = (long)gridDim.x * blockDim.x;
    float4 z = make_float4(0.f, 0.f, 0.f, 0.f);
    float4* s2 = (float4*)g_sums2;
    for (long i = tid; i < (long)NSEG2 * 16; i += stride) s2[i] = z;
    float4* c2 = (float4*)g_cnt2;
    for (long i = tid; i < NSEG2 / 4; i += stride) c2[i] = z;
}

// ---------------- kernel 2: scatter into level-2 ONLY ----------------
__global__ __launch_bounds__(256) void scatter_kernel(
    const float4* __restrict__ feats4,
    const int* __restrict__ coords,
    const int* __restrict__ batch)
{
    int p = blockIdx.x * 256 + threadIdx.x;
    if (p >= NPTS) return;
    int x = coords[3 * p + 0];
    int y = coords[3 * p + 1];
    int z = coords[3 * p + 2];
    int b = batch[p];

    int s2 = (b << 18) | ((x >> 1) << 12) | ((y >> 1) << 6) | (z >> 1);
    g_seg2[p] = s2;
    atomicAdd(&g_cnt2[s2], 1.0f);

    float* p2 = &g_sums2[(long)s2 * 64];
    const float4* f = feats4 + (long)p * 16;
#pragma unroll
    for (int i = 0; i < 16; i++) {
        red_add_v4(p2 + 4 * i, f[i]);
    }
}

// ---------------- kernel 2b: hierarchical reductions ----------------
__global__ __launch_bounds__(256) void reduce4_kernel() {
    int t = blockIdx.x * 256 + threadIdx.x;   // NSEG4 * 16 tasks
    int kc = t & 15;
    int s4 = t >> 4;
    int b = s4 >> 15, x = (s4 >> 10) & 31, y = (s4 >> 5) & 31, z = s4 & 31;
    int base = (b << 18) | ((x << 1) << 12) | ((y << 1) << 6) | (z << 1);
    float4 acc = make_float4(0.f, 0.f, 0.f, 0.f);
#pragma unroll
    for (int d = 0; d < 8; d++) {
        int s2 = base + (((d >> 2) & 1) << 12) + (((d >> 1) & 1) << 6) + (d & 1);
        float4 v = *(const float4*)&g_sums2[(long)s2 * 64 + kc * 4];
        acc.x += v.x; acc.y += v.y; acc.z += v.z; acc.w += v.w;
    }
    *(float4*)&g_sums4[(long)s4 * 64 + kc * 4] = acc;
    if (kc == 0) {
        float c = 0.f;
#pragma unroll
        for (int d = 0; d < 8; d++)
            c += g_cnt2[base + (((d >> 2) & 1) << 12) + (((d >> 1) & 1) << 6) + (d & 1)];
        g_cnt4[s4] = c;
    }
}

__global__ __launch_bounds__(256) void reduce8_kernel() {
    int t = blockIdx.x * 256 + threadIdx.x;   // NSEG8 * 16 tasks
    int kc = t & 15;
    int s8 = t >> 4;
    int b = s8 >> 12, x = (s8 >> 8) & 15, y = (s8 >> 4) & 15, z = s8 & 15;
    int base = (b << 15) | ((x << 1) << 10) | ((y << 1) << 5) | (z << 1);
    float4 acc = make_float4(0.f, 0.f, 0.f, 0.f);
#pragma unroll
    for (int d = 0; d < 8; d++) {
        int s4 = base + (((d >> 2) & 1) << 10) + (((d >> 1) & 1) << 5) + (d & 1);
        float4 v = *(const float4*)&g_sums4[(long)s4 * 64 + kc * 4];
        acc.x += v.x; acc.y += v.y; acc.z += v.z; acc.w += v.w;
    }
    *(float4*)&g_sums8[(long)s8 * 64 + kc * 4] = acc;
    if (kc == 0) {
        float c = 0.f;
#pragma unroll
        for (int d = 0; d < 8; d++)
            c += g_cnt4[base + (((d >> 2) & 1) << 10) + (((d >> 1) & 1) << 5) + (d & 1)];
        g_cnt8[s8] = c;
    }
}

// ---------------- kernel 3: level-0 reduce + base projection ----------------
__global__ __launch_bounds__(256) void l0_kernel(
    const float* __restrict__ W, const float* __restrict__ bias)
{
    int b = blockIdx.x;
    int tid = threadIdx.x;
    __shared__ float sm[4][64];
    __shared__ float smean[64];
    __shared__ float scnt[256];

    int c = tid & 63, g = tid >> 6;
    const float* base = g_sums8 + (long)b * 4096 * 64;
    float acc = 0.f;
    for (int s = g; s < 4096; s += 4) acc += base[s * 64 + c];
    sm[g][c] = acc;

    float ca = 0.f;
    for (int s = tid; s < 4096; s += 256) ca += g_cnt8[b * 4096 + s];
    scnt[tid] = ca;
    __syncthreads();

    for (int off = 128; off > 0; off >>= 1) {
        if (tid < off) scnt[tid] += scnt[tid + off];
        __syncthreads();
    }
    if (tid < 64) {
        smean[tid] = (sm[0][tid] + sm[1][tid] + sm[2][tid] + sm[3][tid])
                   / fmaxf(scnt[0], 1.0f);
    }
    __syncthreads();
    if (tid < 96) {
        float a = bias[tid];
        const float* wr = W + tid * 256;  // global block = cols [0,64)
#pragma unroll 8
        for (int k = 0; k < 64; k++) a += wr[k] * smean[k];
        g_base0[b * COUT + tid] = a;
    }
}

// ---------------- kernel 4: fp32 transforms for levels 8 and 4 ----------------
template <int LEVEL>
__global__ __launch_bounds__(128) void transform_kernel(const float* __restrict__ W)
{
    __shared__ float sh_W[96 * 65];
    __shared__ float sh_m[64 * 36];
    __shared__ int   sh_sid[32];

    int tid  = threadIdx.x;
    int base = blockIdx.x * 32;

    if (tid < 32) sh_sid[tid] = base + tid;

    const int WOFS = (LEVEL == 4) ? 128 : 192;
    for (int j = tid; j < 96 * 64; j += 128) {
        int o = j >> 6, c = j & 63;
        sh_W[o * 65 + c] = W[o * 256 + WOFS + c];
    }
    __syncthreads();

    const float* SUMS = (LEVEL == 4) ? g_sums4 : g_sums8;
    const float* CNT  = (LEVEL == 4) ? g_cnt4  : g_cnt8;

    for (int it = tid; it < 512; it += 128) {
        int slot = it >> 4, kc = it & 15;
        int s = sh_sid[slot];
        float4 v = *(const float4*)&SUMS[(long)s * 64 + kc * 4];
        float inv = 1.0f / fmaxf(CNT[s], 1.0f);
        sh_m[(4 * kc + 0) * 36 + slot] = v.x * inv;
        sh_m[(4 * kc + 1) * 36 + slot] = v.y * inv;
        sh_m[(4 * kc + 2) * 36 + slot] = v.z * inv;
        sh_m[(4 * kc + 3) * 36 + slot] = v.w * inv;
    }
    __syncthreads();

    int rt = tid >> 4, ct = tid & 15;
    int r0 = rt * 4, c0 = ct * 6;

    float acc[4][6];
#pragma unroll
    for (int i = 0; i < 4; i++)
#pragma unroll
        for (int j = 0; j < 6; j++) acc[i][j] = 0.f;

#pragma unroll 8
    for (int k = 0; k < 64; k++) {
        float4 m = *(const float4*)&sh_m[k * 36 + r0];
        float mv[4] = {m.x, m.y, m.z, m.w};
        float w[6];
#pragma unroll
        for (int j = 0; j < 6; j++) w[j] = sh_W[(c0 + j) * 65 + k];
#pragma unroll
        for (int i = 0; i < 4; i++)
#pragma unroll
            for (int j = 0; j < 6; j++) acc[i][j] = fmaf(mv[i], w[j], acc[i][j]);
    }

#pragma unroll
    for (int i = 0; i < 4; i++) {
        int s = sh_sid[r0 + i];
        const float* prev;
        float* Zout;
        if (LEVEL == 8) {
            prev = &g_base0[(s >> 12) * COUT];
            Zout = g_Z8;
        } else {
            int bb = s >> 15, xx = (s >> 10) & 31, yy = (s >> 5) & 31, zz = s & 31;
            int s8 = (bb << 12) | ((xx >> 1) << 8) | ((yy >> 1) << 4) | (zz >> 1);
            prev = &g_Z8[(long)s8 * COUT];
            Zout = g_Z4;
        }
        float* dst = &Zout[(long)s * COUT + c0];
#pragma unroll
        for (int j = 0; j < 6; j++) dst[j] = acc[i][j] + prev[c0 + j];
    }
}

// ---------------- kernel 5: fused level-2 transform + output via mma.sync ----------------
// Precision-compensated bf16x3: A = Ah+Al, B = Bh+Bl,
// D ~= Ah*Bh + Ah*Bl + Al*Bh (fp32 accumulate). out[p] = Z4[s4(p)] + D[p].
#define A_STRIDE 72   // halves per row, padded (bank-conflict-free)
#define B_STRIDE 72

__device__ __forceinline__ void hmma16816(
    float& c0, float& c1, float& c2, float& c3,
    uint32_t a0, uint32_t a1, uint32_t a2, uint32_t a3,
    uint32_t b0, uint32_t b1)
{
    asm volatile(
        "mma.sync.aligned.m16n8k16.row.col.f32.bf16.bf16.f32 "
        "{%0,%1,%2,%3}, {%4,%5,%6,%7}, {%8,%9}, {%0,%1,%2,%3};"
        : "+f"(c0), "+f"(c1), "+f"(c2), "+f"(c3)
        : "r"(a0), "r"(a1), "r"(a2), "r"(a3), "r"(b0), "r"(b1));
}

// split float pair into (hi bf16x2, lo bf16x2)
__device__ __forceinline__ void split2(float x, float y, uint32_t& hi, uint32_t& lo) {
    __nv_bfloat16 hx = __float2bfloat16_rn(x);
    __nv_bfloat16 hy = __float2bfloat16_rn(y);
    __nv_bfloat16 lx = __float2bfloat16_rn(x - __bfloat162float(hx));
    __nv_bfloat16 ly = __float2bfloat16_rn(y - __bfloat162float(hy));
    __nv_bfloat162 h = {hx, hy};
    __nv_bfloat162 l = {lx, ly};
    hi = *(uint32_t*)&h;
    lo = *(uint32_t*)&l;
}

__global__ __launch_bounds__(128) void fused_mma_kernel(
    const float* __restrict__ W, float* __restrict__ out)
{
    __shared__ __align__(16) __nv_bfloat16 sh_Ah[64 * A_STRIDE];
    __shared__ __align__(16) __nv_bfloat16 sh_Al[64 * A_STRIDE];
    __shared__ __align__(16) __nv_bfloat16 sh_Bh[96 * B_STRIDE];
    __shared__ __align__(16) __nv_bfloat16 sh_Bl[96 * B_STRIDE];
    __shared__ int   s_s4[64];
    __shared__ int   s_sid[64];
    __shared__ float s_inv[64];

    int tid  = threadIdx.x;
    int wid  = tid >> 5;
    int lane = tid & 31;
    int pbase = blockIdx.x * 64;

    if (tid < 64) {
        int s2 = g_seg2[pbase + tid];
        s_sid[tid] = s2;
        int bb = s2 >> 18, xx = (s2 >> 12) & 63, yy = (s2 >> 6) & 63, zz = s2 & 63;
        s_s4[tid] = (bb << 15) | ((xx >> 1) << 10) | ((yy >> 1) << 5) | (zz >> 1);
        s_inv[tid] = 1.0f / fmaxf(g_cnt2[s2], 1.0f);
    }
    __syncthreads();

    // stage A: 64 mean rows -> bf16 hi/lo. 64 rows x 16 chunks of 4 floats
    for (int it = tid; it < 1024; it += 128) {
        int slot = it >> 4, kc = it & 15;
        int s = s_sid[slot];
        float inv = s_inv[slot];
        float4 v = *(const float4*)&g_sums2[(long)s * 64 + kc * 4];
        uint32_t h0, l0, h1, l1;
        split2(v.x * inv, v.y * inv, h0, l0);
        split2(v.z * inv, v.w * inv, h1, l1);
        uint32_t* dh = (uint32_t*)&sh_Ah[slot * A_STRIDE + kc * 4];
        uint32_t* dl = (uint32_t*)&sh_Al[slot * A_STRIDE + kc * 4];
        dh[0] = h0; dh[1] = h1;
        dl[0] = l0; dl[1] = l1;
    }
    // stage B: W2 rows (cols 64..127 of W) -> bf16 hi/lo. 96 rows x 16 chunks
    for (int it = tid; it < 1536; it += 128) {
        int o = it >> 4, kc = it & 15;
        float4 v = *(const float4*)&W[o * 256 + 64 + kc * 4];
        uint32_t h0, l0, h1, l1;
        split2(v.x, v.y, h0, l0);
        split2(v.z, v.w, h1, l1);
        uint32_t* dh = (uint32_t*)&sh_Bh[o * B_STRIDE + kc * 4];
        uint32_t* dl = (uint32_t*)&sh_Bl[o * B_STRIDE + kc * 4];
        dh[0] = h0; dh[1] = h1;
        dl[0] = l0; dl[1] = l1;
    }
    __syncthreads();

    // warp computes rows [wid*16, wid*16+16) x 96 outputs
    int warp_m = wid * 16;
    int grp = lane >> 2;         // 0..7
    int qid = lane & 3;          // 0..3

    float acc[12][4];
#pragma unroll
    for (int t = 0; t < 12; t++)
#pragma unroll
        for (int j = 0; j < 4; j++) acc[t][j] = 0.f;

#pragma unroll
    for (int ks = 0; ks < 4; ks++) {
        int k0 = ks * 16 + qid * 2;
        int ra = (warp_m + grp) * A_STRIDE;
        int rb = (warp_m + grp + 8) * A_STRIDE;
        // A fragments hi/lo (row-major m16k16)
        uint32_t ah0 = *(const uint32_t*)&sh_Ah[ra + k0];
        uint32_t ah1 = *(const uint32_t*)&sh_Ah[rb + k0];
        uint32_t ah2 = *(const uint32_t*)&sh_Ah[ra + k0 + 8];
        uint32_t ah3 = *(const uint32_t*)&sh_Ah[rb + k0 + 8];
        uint32_t al0 = *(const uint32_t*)&sh_Al[ra + k0];
        uint32_t al1 = *(const uint32_t*)&sh_Al[rb + k0];
        uint32_t al2 = *(const uint32_t*)&sh_Al[ra + k0 + 8];
        uint32_t al3 = *(const uint32_t*)&sh_Al[rb + k0 + 8];
#pragma unroll
        for (int t = 0; t < 12; t++) {
            int rn = (t * 8 + grp) * B_STRIDE;
            uint32_t bh0 = *(const uint32_t*)&sh_Bh[rn + k0];
            uint32_t bh1 = *(const uint32_t*)&sh_Bh[rn + k0 + 8];
            uint32_t bl0 = *(const uint32_t*)&sh_Bl[rn + k0];
            uint32_t bl1 = *(const uint32_t*)&sh_Bl[rn + k0 + 8];
            hmma16816(acc[t][0], acc[t][1], acc[t][2], acc[t][3],
                      ah0, ah1, ah2, ah3, bh0, bh1);
            hmma16816(acc[t][0], acc[t][1], acc[t][2], acc[t][3],
                      ah0, ah1, ah2, ah3, bl0, bl1);
            hmma16816(acc[t][0], acc[t][1], acc[t][2], acc[t][3],
                      al0, al1, al2, al3, bh0, bh1);
        }
    }

    // epilogue: D rows warp_m+grp and warp_m+grp+8; cols t*8 + qid*2 (+1)
    int slot0 = warp_m + grp;
    int slot1 = slot0 + 8;
    const float* z0 = &g_Z4[(long)s_s4[slot0] * COUT];
    const float* z1 = &g_Z4[(long)s_s4[slot1] * COUT];
    float* d0 = out + (long)(pbase + slot0) * COUT;
    float* d1 = out + (long)(pbase + slot1) * COUT;

#pragma unroll
    for (int t = 0; t < 12; t++) {
        int c = t * 8 + qid * 2;
        float2 za = *(const float2*)&z0[c];
        float2 zb = *(const float2*)&z1[c];
        float2 oa = make_float2(acc[t][0] + za.x, acc[t][1] + za.y);
        float2 ob = make_float2(acc[t][2] + zb.x, acc[t][3] + zb.y);
        *(float2*)&d0[c] = oa;
        *(float2*)&d1[c] = ob;
    }
}

// ---------------- launcher ----------------
extern "C" void kernel_launch(void* const* d_in, const int* in_sizes, int n_in,
                              void* d_out, int out_size)
{
    const float* feats  = (const float*)d_in[0];
    const int*   coords = (const int*)d_in[1];
    const int*   batch  = (const int*)d_in[2];
    const float* W      = (const float*)d_in[3];
    const float* bias   = (const float*)d_in[4];

    zero_kernel<<<2048, 256>>>();
    scatter_kernel<<<NPTS / 256, 256>>>((const float4*)feats, coords, batch);
    reduce4_kernel<<<(NSEG4 * 16) / 256, 256>>>();
    reduce8_kernel<<<(NSEG8 * 16) / 256, 256>>>();
    l0_kernel<<<NB, 256>>>(W, bias);
    transform_kernel<8><<<NSEG8 / 32, 128>>>(W);
    transform_kernel<4><<<NSEG4 / 32, 128>>>(W);
    fused_mma_kernel<<<NPTS / 64, 128>>>(W, (float*)d_out);
}